// round 3
// baseline (speedup 1.0000x reference)
#include <cuda_runtime.h>

#define BDIM 8
#define NDIM 2048
#define DDIM 512
#define P_ASEM 0.6f

// Scratch: esi[b*N+i] = exp(-(si+bias)), esj[b*N+j] = exp(-sj)
__device__ float g_esi[BDIM * NDIM];
__device__ float g_esj[BDIM * NDIM];

// Kernel 1: one warp per row. si = x_row . Wi + b, sj = x_row . Wj,
// stored as exp(-si), exp(-sj).
__global__ void row_dots_kernel(const float* __restrict__ x,
                                const float* __restrict__ W,
                                const float* __restrict__ bias) {
    int warp_id = (blockIdx.x * blockDim.x + threadIdx.x) >> 5;
    int lane = threadIdx.x & 31;
    if (warp_id >= BDIM * NDIM) return;

    const float4* xr = reinterpret_cast<const float4*>(x + (size_t)warp_id * DDIM);
    const float4* Wi = reinterpret_cast<const float4*>(W);
    const float4* Wj = reinterpret_cast<const float4*>(W + DDIM);

    float si = 0.f, sj = 0.f;
#pragma unroll
    for (int k = 0; k < DDIM / 4 / 32; k++) {
        int d4 = lane + k * 32;
        float4 xv = xr[d4];
        float4 wi = Wi[d4];
        float4 wj = Wj[d4];
        si += xv.x * wi.x + xv.y * wi.y + xv.z * wi.z + xv.w * wi.w;
        sj += xv.x * wj.x + xv.y * wj.y + xv.z * wj.z + xv.w * wj.w;
    }
#pragma unroll
    for (int o = 16; o; o >>= 1) {
        si += __shfl_down_sync(0xffffffffu, si, o);
        sj += __shfl_down_sync(0xffffffffu, sj, o);
    }
    if (lane == 0) {
        g_esi[warp_id] = __expf(-(si + bias[0]));
        g_esj[warp_id] = __expf(-sj);
    }
}

// Kernel 2: one block per (b,i) row of 2048 elements.
// sigmoid(si+sj) = 1 / (1 + esi*esj)  -> 1 MUFU.RCP per element.
// out = P*sig + (1-P)*adj
__global__ void __launch_bounds__(256) fuse_kernel(const float* __restrict__ adj,
                                                   float* __restrict__ out) {
    unsigned row = blockIdx.x;               // b*2048 + i
    unsigned b_base = row & ~2047u;          // b*2048
    unsigned tid = threadIdx.x;

    float esi = g_esi[row];                  // uniform per block

    const float4* adj_row = reinterpret_cast<const float4*>(adj) + (size_t)row * (NDIM / 4);
    float4* out_row = reinterpret_cast<float4*>(out) + (size_t)row * (NDIM / 4);
    const float4* esj_row = reinterpret_cast<const float4*>(g_esj + b_base);

    // front-batched loads: 2 adj float4 + 2 esj float4
    float4 a0 = __ldg(adj_row + tid);
    float4 a1 = __ldg(adj_row + tid + 256);
    float4 e0 = esj_row[tid];
    float4 e1 = esj_row[tid + 256];

    float4 o0, o1;
    o0.x = fmaf(P_ASEM, __frcp_rn(fmaf(esi, e0.x, 1.0f)), (1.0f - P_ASEM) * a0.x);
    o0.y = fmaf(P_ASEM, __frcp_rn(fmaf(esi, e0.y, 1.0f)), (1.0f - P_ASEM) * a0.y);
    o0.z = fmaf(P_ASEM, __frcp_rn(fmaf(esi, e0.z, 1.0f)), (1.0f - P_ASEM) * a0.z);
    o0.w = fmaf(P_ASEM, __frcp_rn(fmaf(esi, e0.w, 1.0f)), (1.0f - P_ASEM) * a0.w);
    o1.x = fmaf(P_ASEM, __frcp_rn(fmaf(esi, e1.x, 1.0f)), (1.0f - P_ASEM) * a1.x);
    o1.y = fmaf(P_ASEM, __frcp_rn(fmaf(esi, e1.y, 1.0f)), (1.0f - P_ASEM) * a1.y);
    o1.z = fmaf(P_ASEM, __frcp_rn(fmaf(esi, e1.z, 1.0f)), (1.0f - P_ASEM) * a1.z);
    o1.w = fmaf(P_ASEM, __frcp_rn(fmaf(esi, e1.w, 1.0f)), (1.0f - P_ASEM) * a1.w);

    out_row[tid] = o0;
    out_row[tid + 256] = o1;
}

extern "C" void kernel_launch(void* const* d_in, const int* in_sizes, int n_in,
                              void* d_out, int out_size) {
    const float* x   = (const float*)d_in[0];  // (8, 2048, 512)
    const float* adj = (const float*)d_in[1];  // (8, 2048, 2048)
    const float* W   = (const float*)d_in[2];  // (1, 1024)
    const float* b   = (const float*)d_in[3];  // (1,)
    float* out = (float*)d_out;

    // Kernel 1: 16384 rows, 8 warps/block -> 2048 blocks
    {
        int threads = 256;
        int rows = BDIM * NDIM;
        int warps_per_block = threads / 32;
        int blocks = (rows + warps_per_block - 1) / warps_per_block;
        row_dots_kernel<<<blocks, threads>>>(x, W, b);
    }
    // Kernel 2: one block per row -> 16384 blocks
    fuse_kernel<<<BDIM * NDIM, 256>>>(adj, out);
}